// round 2
// baseline (speedup 1.0000x reference)
#include <cuda_runtime.h>

#define PATCH_NUM 16
#define RPE_NUM   33          // 2*PATCH_NUM + 1
#define NUM_HEADS 8
#define GH        48
#define GW        48
#define NPIX      2304        // 48*48
#define NB        2
#define TAB_ROWS  (3 * RPE_NUM)   // 99 rows of 8 floats

// Scratch for normalized depth (allocation-free: __device__ global).
__device__ __align__(16) float g_znorm[NB * NPIX];

// ---------------------------------------------------------------------------
// Kernel 1: per-image min/max + normalization. One block per image.
// ---------------------------------------------------------------------------
__global__ void minmax_norm_kernel(const float* __restrict__ depth) {
    const int b = blockIdx.x;
    const float* d = depth + b * NPIX;
    __shared__ float s_mn[8], s_mx[8];
    const int tid = threadIdx.x;   // 256 threads

    float mn = 3.4e38f, mx = -3.4e38f;
    for (int idx = tid; idx < NPIX; idx += 256) {
        float v = d[idx];
        mn = fminf(mn, v);
        mx = fmaxf(mx, v);
    }
#pragma unroll
    for (int o = 16; o > 0; o >>= 1) {
        mn = fminf(mn, __shfl_xor_sync(0xffffffffu, mn, o));
        mx = fmaxf(mx, __shfl_xor_sync(0xffffffffu, mx, o));
    }
    if ((tid & 31) == 0) { s_mn[tid >> 5] = mn; s_mx[tid >> 5] = mx; }
    __syncthreads();
    if (tid < 32) {
        mn = (tid < 8) ? s_mn[tid] : 3.4e38f;
        mx = (tid < 8) ? s_mx[tid] : -3.4e38f;
#pragma unroll
        for (int o = 4; o > 0; o >>= 1) {
            mn = fminf(mn, __shfl_xor_sync(0xffffffffu, mn, o));
            mx = fmaxf(mx, __shfl_xor_sync(0xffffffffu, mx, o));
        }
        if (tid == 0) { s_mn[0] = mn; s_mx[0] = mx; }
    }
    __syncthreads();
    mn = s_mn[0];
    const float denom = (s_mx[0] - mn) + 1e-8f;
    for (int idx = tid; idx < NPIX; idx += 256) {
        g_znorm[b * NPIX + idx] = (d[idx] - mn) / denom;
    }
}

// ---------------------------------------------------------------------------
// Kernel 2: one block per (i, b). 576 threads, each handles 4 consecutive j
// (4 j's share a pixel row since 48 % 4 == 0), all 8 heads.
// Output: out[b][h][i][j], stores as float4 per head (STG.128, streaming).
// ---------------------------------------------------------------------------
__global__ __launch_bounds__(576) void rpe_kernel(
    const float4* __restrict__ table4, float* __restrict__ out)
{
    __shared__ float4 s_tab[TAB_ROWS * 2];   // 99 rows x 32B
    const int tid = threadIdx.x;
    const int i   = blockIdx.x;              // query pixel
    const int b   = blockIdx.y;              // batch

    for (int t = tid; t < TAB_ROWS * 2; t += 576) s_tab[t] = table4[t];
    __syncthreads();

    const int   ri = i / GW;
    const int   ci = i - ri * GW;
    const float zi = __ldg(&g_znorm[b * NPIX + i]);

    const int j0  = tid * 4;                 // 576*4 == 2304 == NPIX
    const int rj  = j0 / GW;
    const int cj0 = j0 - rj * GW;            // same row for all 4 j's
    const float4 zj4 = *reinterpret_cast<const float4*>(&g_znorm[b * NPIX + j0]);
    const float zjv[4] = { zj4.x, zj4.y, zj4.z, zj4.w };

    const float XY_SCALE = 16.0f / 47.0f;

    // qy: identical across the 4 j's
    float qy = rintf((float)(ri - rj) * XY_SCALE);
    qy = fminf(fmaxf(qy, -16.0f), 16.0f);
    const int iy = (int)qy + PATCH_NUM + RPE_NUM;
    const float4 ty0 = s_tab[iy * 2 + 0];
    const float4 ty1 = s_tab[iy * 2 + 1];

    float res[NUM_HEADS][4];
#pragma unroll
    for (int k = 0; k < 4; ++k) {
        float qx = rintf((float)(ci - (cj0 + k)) * XY_SCALE);
        qx = fminf(fmaxf(qx, -16.0f), 16.0f);
        const int ix = (int)qx + PATCH_NUM;

        float qz = rintf((zi - zjv[k]) * 16.0f);
        qz = fminf(fmaxf(qz, -16.0f), 16.0f);
        const int iz = (int)qz + PATCH_NUM + 2 * RPE_NUM;

        const float4 tx0 = s_tab[ix * 2 + 0];
        const float4 tx1 = s_tab[ix * 2 + 1];
        const float4 tz0 = s_tab[iz * 2 + 0];
        const float4 tz1 = s_tab[iz * 2 + 1];

        // match reference sum order: (x + y) + z
        res[0][k] = (tx0.x + ty0.x) + tz0.x;
        res[1][k] = (tx0.y + ty0.y) + tz0.y;
        res[2][k] = (tx0.z + ty0.z) + tz0.z;
        res[3][k] = (tx0.w + ty0.w) + tz0.w;
        res[4][k] = (tx1.x + ty1.x) + tz1.x;
        res[5][k] = (tx1.y + ty1.y) + tz1.y;
        res[6][k] = (tx1.z + ty1.z) + tz1.z;
        res[7][k] = (tx1.w + ty1.w) + tz1.w;
    }

    const size_t plane = (size_t)NPIX * NPIX;
    const size_t base  = ((size_t)(b * NUM_HEADS) * NPIX + (size_t)i) * NPIX + j0;
#pragma unroll
    for (int h = 0; h < NUM_HEADS; ++h) {
        float4 v = make_float4(res[h][0], res[h][1], res[h][2], res[h][3]);
        __stcs(reinterpret_cast<float4*>(out + base + (size_t)h * plane), v);
    }
}

// ---------------------------------------------------------------------------
extern "C" void kernel_launch(void* const* d_in, const int* in_sizes, int n_in,
                              void* d_out, int out_size) {
    const float*  depth = (const float*)d_in[0];     // (2,48,48) f32
    const float4* table = (const float4*)d_in[1];    // (99,8) f32 -> 198 float4
    float* out = (float*)d_out;                      // (2,8,2304,2304) f32

    minmax_norm_kernel<<<NB, 256>>>(depth);

    dim3 grid(NPIX, NB);
    rpe_kernel<<<grid, 576>>>(table, out);
}

// round 3
// speedup vs baseline: 1.0227x; 1.0227x over previous
#include <cuda_runtime.h>

#define PATCH_NUM 16
#define RPE_NUM   33          // 2*PATCH_NUM + 1
#define NUM_HEADS 8
#define GH        48
#define GW        48
#define NPIX      2304        // 48*48
#define NB        2

// Scratch for normalized depth (allocation-free: __device__ global).
__device__ __align__(16) float g_znorm[NB * NPIX];

// ---------------------------------------------------------------------------
// Kernel 1: per-image min/max + normalization. One block per image.
// ---------------------------------------------------------------------------
__global__ void minmax_norm_kernel(const float* __restrict__ depth) {
    const int b = blockIdx.x;
    const float* d = depth + b * NPIX;
    __shared__ float s_mn[8], s_mx[8];
    const int tid = threadIdx.x;   // 256 threads

    float mn = 3.4e38f, mx = -3.4e38f;
    for (int idx = tid; idx < NPIX; idx += 256) {
        float v = d[idx];
        mn = fminf(mn, v);
        mx = fmaxf(mx, v);
    }
#pragma unroll
    for (int o = 16; o > 0; o >>= 1) {
        mn = fminf(mn, __shfl_xor_sync(0xffffffffu, mn, o));
        mx = fmaxf(mx, __shfl_xor_sync(0xffffffffu, mx, o));
    }
    if ((tid & 31) == 0) { s_mn[tid >> 5] = mn; s_mx[tid >> 5] = mx; }
    __syncthreads();
    if (tid < 32) {
        mn = (tid < 8) ? s_mn[tid] : 3.4e38f;
        mx = (tid < 8) ? s_mx[tid] : -3.4e38f;
#pragma unroll
        for (int o = 4; o > 0; o >>= 1) {
            mn = fminf(mn, __shfl_xor_sync(0xffffffffu, mn, o));
            mx = fmaxf(mx, __shfl_xor_sync(0xffffffffu, mx, o));
        }
        if (tid == 0) { s_mn[0] = mn; s_mx[0] = mx; }
    }
    __syncthreads();
    mn = s_mn[0];
    const float denom = (s_mx[0] - mn) + 1e-8f;
    for (int idx = tid; idx < NPIX; idx += 256) {
        g_znorm[b * NPIX + idx] = (d[idx] - mn) / denom;
    }
}

// ---------------------------------------------------------------------------
// Kernel 2: one block per (i, b).
//
// Stage A (per block): precompute s_xy[h][j] = table[ix(ci,cj)][h] +
//                      table[iy(ri,rj)][h] for all 2304 j, stored as 8
//                      per-head planes so the main loop reads them with
//                      conflict-free LDS.128 (16B stride across lanes).
// Stage B: each thread handles 4 consecutive j; z gather from two 16B-stride
//          float4 arrays; 8 x STG.128 streaming stores per thread.
// ---------------------------------------------------------------------------
// dynamic smem layout:
//   [0)                 float s_xy[8 * 2304]          (73728 B)
//   [73728)             float4 s_tz0[33]              (528 B)
//   [74256)             float4 s_tz1[33]              (528 B)
#define SMEM_BYTES (NUM_HEADS * NPIX * 4 + 2 * RPE_NUM * 16)

extern __shared__ float s_dyn[];

__global__ __launch_bounds__(576, 2) void rpe_kernel(
    const float4* __restrict__ table4, float* __restrict__ out)
{
    float*  s_xy  = s_dyn;                                   // [8][2304]
    float4* s_tz0 = reinterpret_cast<float4*>(s_dyn + NUM_HEADS * NPIX);
    float4* s_tz1 = s_tz0 + RPE_NUM;

    const int tid = threadIdx.x;
    const int i   = blockIdx.x;              // query pixel
    const int b   = blockIdx.y;              // batch

    const int ri = i / GW;
    const int ci = i - ri * GW;
    const float XY_SCALE = 16.0f / 47.0f;

    // ---- Stage A: z table rows (idx+66) into 16B-stride arrays ----
    if (tid < RPE_NUM) {
        s_tz0[tid] = __ldg(&table4[(2 * RPE_NUM + tid) * 2 + 0]);
        s_tz1[tid] = __ldg(&table4[(2 * RPE_NUM + tid) * 2 + 1]);
    }

    // ---- Stage A: xy combined planes ----
#pragma unroll
    for (int it = 0; it < 4; ++it) {
        const int idx = tid + it * 576;      // 4*576 == 2304
        const int rj  = idx / GW;
        const int cj  = idx - rj * GW;

        float qx = rintf((float)(ci - cj) * XY_SCALE);
        qx = fminf(fmaxf(qx, -16.0f), 16.0f);
        const int ix = (int)qx + PATCH_NUM;

        float qy = rintf((float)(ri - rj) * XY_SCALE);
        qy = fminf(fmaxf(qy, -16.0f), 16.0f);
        const int iy = (int)qy + PATCH_NUM + RPE_NUM;

        const float4 x0 = __ldg(&table4[ix * 2 + 0]);
        const float4 x1 = __ldg(&table4[ix * 2 + 1]);
        const float4 y0 = __ldg(&table4[iy * 2 + 0]);
        const float4 y1 = __ldg(&table4[iy * 2 + 1]);

        // (x + y), per-head planes; lanes write consecutive idx -> no conflicts
        s_xy[0 * NPIX + idx] = x0.x + y0.x;
        s_xy[1 * NPIX + idx] = x0.y + y0.y;
        s_xy[2 * NPIX + idx] = x0.z + y0.z;
        s_xy[3 * NPIX + idx] = x0.w + y0.w;
        s_xy[4 * NPIX + idx] = x1.x + y1.x;
        s_xy[5 * NPIX + idx] = x1.y + y1.y;
        s_xy[6 * NPIX + idx] = x1.z + y1.z;
        s_xy[7 * NPIX + idx] = x1.w + y1.w;
    }
    __syncthreads();

    // ---- Stage B ----
    const float zi = __ldg(&g_znorm[b * NPIX + i]);
    const int j0 = tid * 4;                  // 576*4 == 2304
    const float4 zj4 = *reinterpret_cast<const float4*>(&g_znorm[b * NPIX + j0]);
    const float zjv[4] = { zj4.x, zj4.y, zj4.z, zj4.w };

    // z rows for the 4 j's
    float4 z0[4], z1[4];
#pragma unroll
    for (int k = 0; k < 4; ++k) {
        float qz = rintf((zi - zjv[k]) * 16.0f);
        qz = fminf(fmaxf(qz, -16.0f), 16.0f);
        const int iz = (int)qz + PATCH_NUM;
        z0[k] = s_tz0[iz];
        z1[k] = s_tz1[iz];
    }

    const size_t plane = (size_t)NPIX * NPIX;
    const size_t base  = ((size_t)(b * NUM_HEADS) * NPIX + (size_t)i) * NPIX + j0;

    // heads 0..3 come from z0 components, heads 4..7 from z1
#pragma unroll
    for (int h = 0; h < 4; ++h) {
        const float4 xy = *reinterpret_cast<const float4*>(&s_xy[h * NPIX + j0]);
        const float zh0 = (h == 0) ? z0[0].x : (h == 1) ? z0[0].y : (h == 2) ? z0[0].z : z0[0].w;
        const float zh1 = (h == 0) ? z0[1].x : (h == 1) ? z0[1].y : (h == 2) ? z0[1].z : z0[1].w;
        const float zh2 = (h == 0) ? z0[2].x : (h == 1) ? z0[2].y : (h == 2) ? z0[2].z : z0[2].w;
        const float zh3 = (h == 0) ? z0[3].x : (h == 1) ? z0[3].y : (h == 2) ? z0[3].z : z0[3].w;
        float4 v = make_float4(xy.x + zh0, xy.y + zh1, xy.z + zh2, xy.w + zh3);
        __stcs(reinterpret_cast<float4*>(out + base + (size_t)h * plane), v);
    }
#pragma unroll
    for (int h = 0; h < 4; ++h) {
        const float4 xy = *reinterpret_cast<const float4*>(&s_xy[(h + 4) * NPIX + j0]);
        const float zh0 = (h == 0) ? z1[0].x : (h == 1) ? z1[0].y : (h == 2) ? z1[0].z : z1[0].w;
        const float zh1 = (h == 0) ? z1[1].x : (h == 1) ? z1[1].y : (h == 2) ? z1[1].z : z1[1].w;
        const float zh2 = (h == 0) ? z1[2].x : (h == 1) ? z1[2].y : (h == 2) ? z1[2].z : z1[2].w;
        const float zh3 = (h == 0) ? z1[3].x : (h == 1) ? z1[3].y : (h == 2) ? z1[3].z : z1[3].w;
        float4 v = make_float4(xy.x + zh0, xy.y + zh1, xy.z + zh2, xy.w + zh3);
        __stcs(reinterpret_cast<float4*>(out + base + (size_t)(h + 4) * plane), v);
    }
}

// ---------------------------------------------------------------------------
extern "C" void kernel_launch(void* const* d_in, const int* in_sizes, int n_in,
                              void* d_out, int out_size) {
    const float*  depth = (const float*)d_in[0];     // (2,48,48) f32
    const float4* table = (const float4*)d_in[1];    // (99,8) f32 -> 198 float4
    float* out = (float*)d_out;                      // (2,8,2304,2304) f32

    static int configured = 0;
    if (!configured) {
        cudaFuncSetAttribute(rpe_kernel,
                             cudaFuncAttributeMaxDynamicSharedMemorySize,
                             SMEM_BYTES);
        configured = 1;
    }

    minmax_norm_kernel<<<NB, 256>>>(depth);

    dim3 grid(NPIX, NB);
    rpe_kernel<<<grid, 576, SMEM_BYTES>>>(table, out);
}

// round 4
// speedup vs baseline: 1.5003x; 1.4669x over previous
#include <cuda_runtime.h>

#define PATCH_NUM 16
#define RPE_NUM   33          // 2*PATCH_NUM + 1
#define NUM_HEADS 8
#define GH        48
#define GW        48
#define NPIX      2304        // 48*48
#define NB        2
#define TAB_ROWS  (3 * RPE_NUM)   // 99

// Scratch for normalized depth (allocation-free: __device__ global).
__device__ __align__(16) float g_znorm[NB * NPIX];

// ---------------------------------------------------------------------------
// Kernel 1: per-image min/max + normalization. One block per image.
// ---------------------------------------------------------------------------
__global__ void minmax_norm_kernel(const float* __restrict__ depth) {
    const int b = blockIdx.x;
    const float* d = depth + b * NPIX;
    __shared__ float s_mn[8], s_mx[8];
    const int tid = threadIdx.x;   // 256 threads

    float mn = 3.4e38f, mx = -3.4e38f;
    for (int idx = tid; idx < NPIX; idx += 256) {
        float v = d[idx];
        mn = fminf(mn, v);
        mx = fmaxf(mx, v);
    }
#pragma unroll
    for (int o = 16; o > 0; o >>= 1) {
        mn = fminf(mn, __shfl_xor_sync(0xffffffffu, mn, o));
        mx = fmaxf(mx, __shfl_xor_sync(0xffffffffu, mx, o));
    }
    if ((tid & 31) == 0) { s_mn[tid >> 5] = mn; s_mx[tid >> 5] = mx; }
    __syncthreads();
    if (tid < 32) {
        mn = (tid < 8) ? s_mn[tid] : 3.4e38f;
        mx = (tid < 8) ? s_mx[tid] : -3.4e38f;
#pragma unroll
        for (int o = 4; o > 0; o >>= 1) {
            mn = fminf(mn, __shfl_xor_sync(0xffffffffu, mn, o));
            mx = fmaxf(mx, __shfl_xor_sync(0xffffffffu, mx, o));
        }
        if (tid == 0) { s_mn[0] = mn; s_mx[0] = mx; }
    }
    __syncthreads();
    mn = s_mn[0];
    const float denom = (s_mx[0] - mn) + 1e-8f;
    for (int idx = tid; idx < NPIX; idx += 256) {
        g_znorm[b * NPIX + idx] = (d[idx] - mn) / denom;
    }
}

// ---------------------------------------------------------------------------
// Kernel 2: one block per (i, b). 576 threads x 4 consecutive j each.
//
// Table replicated 8x in smem: s_tab[half][row][copy], rows 128B apart.
// Each thread uses copy = tid & 7, so within every 8-lane LDS.128 phase,
// lane l hits bank-group l -> ALL gathers conflict-free (incl. z).
// ---------------------------------------------------------------------------
__global__ __launch_bounds__(576, 2) void rpe_kernel(
    const float4* __restrict__ table4, float* __restrict__ out)
{
    __shared__ __align__(128) float4 s_tab[2][TAB_ROWS][8];  // 25344 B

    const int tid = threadIdx.x;
    const int i   = blockIdx.x;              // query pixel
    const int b   = blockIdx.y;              // batch

    // Prologue: replicate table (2 halves x 99 rows x 8 copies = 1584 entries)
    for (int e = tid; e < 2 * TAB_ROWS * 8; e += 576) {
        const int half = e >> 3 >= TAB_ROWS ? 1 : 0;
        const int rem  = e - half * TAB_ROWS * 8;
        const int row  = rem >> 3;
        const int cp   = rem & 7;
        s_tab[half][row][cp] = __ldg(&table4[row * 2 + half]);
    }
    __syncthreads();

    const int   ri = i / GW;
    const int   ci = i - ri * GW;
    const float zi = __ldg(&g_znorm[b * NPIX + i]);
    const int   cp = tid & 7;                // replication copy for this lane

    const int j0  = tid * 4;                 // 576*4 == 2304 == NPIX
    const int rj  = j0 / GW;
    const int cj0 = j0 - rj * GW;            // 4 j's share a pixel row
    const float4 zj4 = *reinterpret_cast<const float4*>(&g_znorm[b * NPIX + j0]);
    const float zjv[4] = { zj4.x, zj4.y, zj4.z, zj4.w };

    const float XY_SCALE = 16.0f / 47.0f;

    // indices (shared across the two table halves)
    float qy = rintf((float)(ri - rj) * XY_SCALE);
    qy = fminf(fmaxf(qy, -16.0f), 16.0f);
    const int iy = (int)qy + PATCH_NUM + RPE_NUM;

    int ixv[4], izv[4];
#pragma unroll
    for (int k = 0; k < 4; ++k) {
        float qx = rintf((float)(ci - (cj0 + k)) * XY_SCALE);
        qx = fminf(fmaxf(qx, -16.0f), 16.0f);
        ixv[k] = (int)qx + PATCH_NUM;

        float qz = rintf((zi - zjv[k]) * 16.0f);
        qz = fminf(fmaxf(qz, -16.0f), 16.0f);
        izv[k] = (int)qz + PATCH_NUM + 2 * RPE_NUM;
    }

    const size_t plane = (size_t)NPIX * NPIX;
    const size_t base  = ((size_t)(b * NUM_HEADS) * NPIX + (size_t)i) * NPIX + j0;

    // process half=0 (heads 0..3) then half=1 (heads 4..7) to cap live regs
#pragma unroll
    for (int half = 0; half < 2; ++half) {
        const float4 ty = s_tab[half][iy][cp];
        float r0[4], r1[4], r2[4], r3[4];
#pragma unroll
        for (int k = 0; k < 4; ++k) {
            const float4 tx = s_tab[half][ixv[k]][cp];
            const float4 tz = s_tab[half][izv[k]][cp];
            // match reference sum order: (x + y) + z
            r0[k] = (tx.x + ty.x) + tz.x;
            r1[k] = (tx.y + ty.y) + tz.y;
            r2[k] = (tx.z + ty.z) + tz.z;
            r3[k] = (tx.w + ty.w) + tz.w;
        }
        const size_t hb = base + (size_t)(half * 4) * plane;
        __stcs(reinterpret_cast<float4*>(out + hb + 0 * plane),
               make_float4(r0[0], r0[1], r0[2], r0[3]));
        __stcs(reinterpret_cast<float4*>(out + hb + 1 * plane),
               make_float4(r1[0], r1[1], r1[2], r1[3]));
        __stcs(reinterpret_cast<float4*>(out + hb + 2 * plane),
               make_float4(r2[0], r2[1], r2[2], r2[3]));
        __stcs(reinterpret_cast<float4*>(out + hb + 3 * plane),
               make_float4(r3[0], r3[1], r3[2], r3[3]));
    }
}

// ---------------------------------------------------------------------------
extern "C" void kernel_launch(void* const* d_in, const int* in_sizes, int n_in,
                              void* d_out, int out_size) {
    const float*  depth = (const float*)d_in[0];     // (2,48,48) f32
    const float4* table = (const float4*)d_in[1];    // (99,8) f32 -> 198 float4
    float* out = (float*)d_out;                      // (2,8,2304,2304) f32

    minmax_norm_kernel<<<NB, 256>>>(depth);

    dim3 grid(NPIX, NB);
    rpe_kernel<<<grid, 576>>>(table, out);
}

// round 5
// speedup vs baseline: 1.6601x; 1.1066x over previous
#include <cuda_runtime.h>

#define PATCH_NUM 16
#define RPE_NUM   33          // 2*PATCH_NUM + 1
#define NUM_HEADS 8
#define GH        48
#define GW        48
#define NPIX      2304        // 48*48
#define NB        2
#define TAB_ROWS  (3 * RPE_NUM)   // 99
#define NI        2               // query pixels per block

// Scratch for normalized depth (allocation-free: __device__ global).
__device__ __align__(16) float g_znorm[NB * NPIX];

// ---------------------------------------------------------------------------
// Kernel 1: per-image min/max + normalization. One block per image.
// ---------------------------------------------------------------------------
__global__ void minmax_norm_kernel(const float* __restrict__ depth) {
    const int b = blockIdx.x;
    const float* d = depth + b * NPIX;
    __shared__ float s_mn[8], s_mx[8];
    const int tid = threadIdx.x;   // 256 threads

    float mn = 3.4e38f, mx = -3.4e38f;
    for (int idx = tid; idx < NPIX; idx += 256) {
        float v = d[idx];
        mn = fminf(mn, v);
        mx = fmaxf(mx, v);
    }
#pragma unroll
    for (int o = 16; o > 0; o >>= 1) {
        mn = fminf(mn, __shfl_xor_sync(0xffffffffu, mn, o));
        mx = fmaxf(mx, __shfl_xor_sync(0xffffffffu, mx, o));
    }
    if ((tid & 31) == 0) { s_mn[tid >> 5] = mn; s_mx[tid >> 5] = mx; }
    __syncthreads();
    if (tid < 32) {
        mn = (tid < 8) ? s_mn[tid] : 3.4e38f;
        mx = (tid < 8) ? s_mx[tid] : -3.4e38f;
#pragma unroll
        for (int o = 4; o > 0; o >>= 1) {
            mn = fminf(mn, __shfl_xor_sync(0xffffffffu, mn, o));
            mx = fmaxf(mx, __shfl_xor_sync(0xffffffffu, mx, o));
        }
        if (tid == 0) { s_mn[0] = mn; s_mx[0] = mx; }
    }
    __syncthreads();
    mn = s_mn[0];
    const float denom = (s_mx[0] - mn) + 1e-8f;
    for (int idx = tid; idx < NPIX; idx += 256) {
        g_znorm[b * NPIX + idx] = (d[idx] - mn) / denom;
    }
}

// ---------------------------------------------------------------------------
// Kernel 2: one block per (i-pair, b). 576 threads x 4 consecutive j each,
// NI=2 query pixels per block (prologue + zj loads amortized).
//
// Table replicated 8x in smem: s_tab[half][row][copy], rows 128B apart.
// Each thread uses copy = tid & 7, so within every 8-lane LDS.128 phase,
// lane l hits bank-group l -> ALL gathers conflict-free (incl. z).
// ---------------------------------------------------------------------------
__global__ __launch_bounds__(576, 2) void rpe_kernel(
    const float4* __restrict__ table4, float* __restrict__ out)
{
    __shared__ __align__(128) float4 s_tab[2][TAB_ROWS][8];  // 25344 B

    const int tid = threadIdx.x;
    const int i0  = blockIdx.x * NI;         // first query pixel of this block
    const int b   = blockIdx.y;              // batch

    // Prologue: replicate table (2 halves x 99 rows x 8 copies = 1584 entries)
    for (int e = tid; e < 2 * TAB_ROWS * 8; e += 576) {
        const int half = (e >> 3) >= TAB_ROWS ? 1 : 0;
        const int rem  = e - half * TAB_ROWS * 8;
        const int row  = rem >> 3;
        const int cp0  = rem & 7;
        s_tab[half][row][cp0] = __ldg(&table4[row * 2 + half]);
    }
    __syncthreads();

    const int cp = tid & 7;                  // replication copy for this lane

    const int j0  = tid * 4;                 // 576*4 == 2304 == NPIX
    const int rj  = j0 / GW;
    const int cj0 = j0 - rj * GW;            // 4 j's share a pixel row
    const float4 zj4 = *reinterpret_cast<const float4*>(&g_znorm[b * NPIX + j0]);
    const float zjv[4] = { zj4.x, zj4.y, zj4.z, zj4.w };

    const float XY_SCALE = 16.0f / 47.0f;
    const size_t plane = (size_t)NPIX * NPIX;

#pragma unroll
    for (int ii = 0; ii < NI; ++ii) {
        const int i  = i0 + ii;
        const int ri = i / GW;
        const int ci = i - ri * GW;
        const float zi = __ldg(&g_znorm[b * NPIX + i]);

        float qy = rintf((float)(ri - rj) * XY_SCALE);
        qy = fminf(fmaxf(qy, -16.0f), 16.0f);
        const int iy = (int)qy + PATCH_NUM + RPE_NUM;

        int ixv[4], izv[4];
#pragma unroll
        for (int k = 0; k < 4; ++k) {
            float qx = rintf((float)(ci - (cj0 + k)) * XY_SCALE);
            qx = fminf(fmaxf(qx, -16.0f), 16.0f);
            ixv[k] = (int)qx + PATCH_NUM;

            float qz = rintf((zi - zjv[k]) * 16.0f);
            qz = fminf(fmaxf(qz, -16.0f), 16.0f);
            izv[k] = (int)qz + PATCH_NUM + 2 * RPE_NUM;
        }

        const size_t base = ((size_t)(b * NUM_HEADS) * NPIX + (size_t)i) * NPIX + j0;

        // half=0 -> heads 0..3, half=1 -> heads 4..7 (caps live registers)
#pragma unroll
        for (int half = 0; half < 2; ++half) {
            const float4 ty = s_tab[half][iy][cp];
            float r0[4], r1[4], r2[4], r3[4];
#pragma unroll
            for (int k = 0; k < 4; ++k) {
                const float4 tx = s_tab[half][ixv[k]][cp];
                const float4 tz = s_tab[half][izv[k]][cp];
                // match reference sum order: (x + y) + z
                r0[k] = (tx.x + ty.x) + tz.x;
                r1[k] = (tx.y + ty.y) + tz.y;
                r2[k] = (tx.z + ty.z) + tz.z;
                r3[k] = (tx.w + ty.w) + tz.w;
            }
            const size_t hb = base + (size_t)(half * 4) * plane;
            __stcs(reinterpret_cast<float4*>(out + hb + 0 * plane),
                   make_float4(r0[0], r0[1], r0[2], r0[3]));
            __stcs(reinterpret_cast<float4*>(out + hb + 1 * plane),
                   make_float4(r1[0], r1[1], r1[2], r1[3]));
            __stcs(reinterpret_cast<float4*>(out + hb + 2 * plane),
                   make_float4(r2[0], r2[1], r2[2], r2[3]));
            __stcs(reinterpret_cast<float4*>(out + hb + 3 * plane),
                   make_float4(r3[0], r3[1], r3[2], r3[3]));
        }
    }
}

// ---------------------------------------------------------------------------
extern "C" void kernel_launch(void* const* d_in, const int* in_sizes, int n_in,
                              void* d_out, int out_size) {
    const float*  depth = (const float*)d_in[0];     // (2,48,48) f32
    const float4* table = (const float4*)d_in[1];    // (99,8) f32 -> 198 float4
    float* out = (float*)d_out;                      // (2,8,2304,2304) f32

    minmax_norm_kernel<<<NB, 256>>>(depth);

    dim3 grid(NPIX / NI, NB);
    rpe_kernel<<<grid, 576>>>(table, out);
}